// round 12
// baseline (speedup 1.0000x reference)
#include <cuda_runtime.h>
#include <cuda_fp16.h>
#include <cstdint>
#include <math.h>

// Problem constants
#define PP    16
#define EE    512
#define HH    512
#define NTOT  8192

// Tiling: 2 CTAs/SM; warp-private 3-stage B pipeline; swizzled smem
#define MT       64
#define THREADS  128   // 4 warps: warp tile 64x64

#define SA     0                 // A: 64 rows x 1024B, XOR-swizzled
#define SB     65536             // B: 4 warps x 3 bufs x 4096B
#define BBUF   4096
#define BWARP  (3 * BBUF)
#define SMEM_BYTES 114688        // -> 2 CTAs/SM

// Static device scratch
// Pipeline-order weights: [p][g=0..31][row 0..255][k 0..31] halves
__device__ __align__(16) __half g_w0t[(size_t)PP * HH * EE];
__device__ __align__(16) __half g_w1t[(size_t)PP * HH * HH];
__device__ __align__(16) __half g_h[(size_t)PP * NTOT * 256];  // first-computed half staged

// ---------------------------------------------------------------------------
// Base-ISA PTX helpers
// ---------------------------------------------------------------------------
__device__ __forceinline__ uint32_t smem_u32(const void* p) {
    uint32_t a;
    asm("{ .reg .u64 t; cvta.to.shared.u64 t, %1; cvt.u32.u64 %0, t; }"
        : "=r"(a) : "l"(p));
    return a;
}
__device__ __forceinline__ void cp16(uint32_t dst, const void* src) {
    asm volatile("cp.async.cg.shared.global [%0], [%1], 16;" :: "r"(dst), "l"(src));
}
__device__ __forceinline__ void cp_commit() { asm volatile("cp.async.commit_group;" ::: "memory"); }
template <int N>
__device__ __forceinline__ void cp_wait() { asm volatile("cp.async.wait_group %0;" :: "n"(N) : "memory"); }

__device__ __forceinline__ void ldm4(uint32_t* r, uint32_t a) {
    asm volatile("ldmatrix.sync.aligned.m8n8.x4.shared.b16 {%0,%1,%2,%3}, [%4];"
                 : "=r"(r[0]), "=r"(r[1]), "=r"(r[2]), "=r"(r[3]) : "r"(a));
}
__device__ __forceinline__ void mma16816(float* c, const uint32_t* a, const uint32_t* b) {
    asm volatile(
        "mma.sync.aligned.m16n8k16.row.col.f32.f16.f16.f32 "
        "{%0,%1,%2,%3}, {%4,%5,%6,%7}, {%8,%9}, {%0,%1,%2,%3};"
        : "+f"(c[0]), "+f"(c[1]), "+f"(c[2]), "+f"(c[3])
        : "r"(a[0]), "r"(a[1]), "r"(a[2]), "r"(a[3]), "r"(b[0]), "r"(b[1]));
}

// Issue B chunk g (0..31) into pipeline slot (0..2); 4KB contiguous slab/warp
__device__ __forceinline__ void issue_b(uint32_t bw_base, const char* wbase,
                                        int slot, int g, uint32_t lseed, uint32_t ldst) {
    uint32_t bdst = bw_base + (uint32_t)slot * BBUF + ldst;
    const char* src = wbase + (size_t)g * 16384 + lseed;
#pragma unroll
    for (int it = 0; it < 8; it++)
        cp16(bdst + it * 512, src + it * 512);
    cp_commit();
}

// One K-chunk of MMAs (64 HMMA) against buffer slot; kc = K position 0..15
__device__ __forceinline__ void compute_chunk(float (*acc)[8][4], uint32_t sbA,
                                              uint32_t bbase, const uint32_t* aoff,
                                              const uint32_t* boff, int kc) {
#pragma unroll
    for (int ks = 0; ks < 2; ks++) {
        uint32_t kbits = ((uint32_t)kc << 6) ^ ((uint32_t)ks << 5);
        uint32_t aR[4][4];
#pragma unroll
        for (int mf = 0; mf < 4; mf++)
            ldm4(aR[mf], sbA + (aoff[mf] ^ kbits));
        uint32_t bR[4][4];
#pragma unroll
        for (int nf2 = 0; nf2 < 4; nf2++)
            ldm4(bR[nf2], bbase + (boff[nf2] ^ ((uint32_t)ks << 5)));
#pragma unroll
        for (int mf = 0; mf < 4; mf++)
#pragma unroll
            for (int nf = 0; nf < 8; nf++)
                mma16816(acc[mf][nf], aR[mf], &bR[nf >> 1][(nf & 1) * 2]);
    }
}

// ---------------------------------------------------------------------------
// Pre-pass: both weights, one launch. W [p][kin][cout] fp32 -> Wt[p][g][n][k]
//   g = (cout/256)*16 + kin/32, n = cout%256, k = kin%32
// ---------------------------------------------------------------------------
__global__ void conv_w_kernel(const float* __restrict__ W0f,
                              const float* __restrict__ W1f) {
    __shared__ float tile[32][33];
    int which = blockIdx.z >> 4;
    int p = blockIdx.z & 15;
    const float* w = (which ? W1f : W0f) + (size_t)p * 512 * 512;
    __half* wt = (which ? g_w1t : g_w0t) + (size_t)p * 512 * 512;
    int c0 = blockIdx.x * 32;   // cout tile
    int r0 = blockIdx.y * 32;   // kin tile
    for (int j = threadIdx.y; j < 32; j += 8)
        tile[j][threadIdx.x] = w[(size_t)(r0 + j) * 512 + c0 + threadIdx.x];
    __syncthreads();
    int g = (c0 >> 8) * 16 + (r0 >> 5);
    int nloc = c0 & 255;
    for (int jj = threadIdx.y; jj < 32; jj += 8)
        wt[((size_t)g * 256 + nloc + jj) * 32 + threadIdx.x] =
            __float2half(tile[threadIdx.x][jj]);
}

// ---------------------------------------------------------------------------
// Fused MLP: 4 warps, 64x64 warp tiles, staggered co-resident CTAs
// ---------------------------------------------------------------------------
__global__ void __launch_bounds__(THREADS, 2)
mlp_fused(const float* __restrict__ e,
          const float* __restrict__ b0, const float* __restrict__ b1,
          const float* __restrict__ W2, const float* __restrict__ b2,
          float* __restrict__ out) {
    extern __shared__ char smem[];
    uint32_t sb = smem_u32(smem);
    int tid = threadIdx.x;
    int lane = tid & 31, wid = tid >> 5;
    int wn = wid;
    int p = blockIdx.x >> 7;
    int mt = blockIdx.x & 127;
    int m0 = mt * MT;
    int swap = (blockIdx.x >> 2) & 1;   // co-resident pair (bid, bid+148) differ in bit 2

    // lane constants
    int selA = lane >> 3;
    int a_row  = (selA & 1) * 8 + (lane & 7);
    int a_koff = (selA >> 1);
    int b_row  = (lane >> 4) * 8 + (lane & 7);
    int b_kchk = (lane >> 3) & 1;

    uint32_t aoff[4], boff[4];
#pragma unroll
    for (int mf = 0; mf < 4; mf++) {
        int row = mf * 16 + a_row;
        aoff[mf] = (uint32_t)row * 1024 + (uint32_t)(((row & 7) ^ a_koff) << 4);
    }
#pragma unroll
    for (int nf2 = 0; nf2 < 4; nf2++) {
        int n = nf2 * 16 + b_row;
        boff[nf2] = (uint32_t)n * 64 + (uint32_t)((((n >> 1) & 3) ^ b_kchk) << 4);
    }

    uint32_t bw_base = sb + SB + (uint32_t)wn * BWARP;
    uint32_t lseed = (uint32_t)wn * 4096 + (uint32_t)(lane >> 2) * 64 + (uint32_t)(lane & 3) * 16;
    uint32_t ldst  = (uint32_t)(lane >> 2) * 64 +
                     (uint32_t)(((lane & 3) ^ ((lane >> 3) & 3)) << 4);

    const char* w0base = (const char*)(g_w0t + (size_t)p * 512 * 512);
    const char* w1base = (const char*)(g_w1t + (size_t)p * 512 * 512);

    // Prologue: B0/B1 of layer-0's FIRST group in flight, then e fp32->fp16 into A
    {
        int g0 = swap * 16;
        issue_b(bw_base, w0base, 0, g0,     lseed, ldst);
        issue_b(bw_base, w0base, 1, g0 + 1, lseed, ldst);
    }
#pragma unroll 4
    for (int i = tid; i < 64 * 64; i += THREADS) {   // 4096 x 16B chunks
        int row = i >> 6, c = i & 63;
        const float4* s4 = (const float4*)(e + (size_t)(m0 + row) * 512 + c * 8);
        float4 v0 = s4[0], v1 = s4[1];
        __half2 h0 = __floats2half2_rn(v0.x, v0.y);
        __half2 h1 = __floats2half2_rn(v0.z, v0.w);
        __half2 h2 = __floats2half2_rn(v1.x, v1.y);
        __half2 h3 = __floats2half2_rn(v1.z, v1.w);
        uint4 pk;
        pk.x = *(uint32_t*)&h0; pk.y = *(uint32_t*)&h1;
        pk.z = *(uint32_t*)&h2; pk.w = *(uint32_t*)&h3;
        *(uint4*)(smem + (uint32_t)row * 1024 + (uint32_t)((c ^ (row & 7)) << 4)) = pk;
    }
    __syncthreads();

    float pacc[4][2] = {{0.f,0.f},{0.f,0.f},{0.f,0.f},{0.f,0.f}};

#pragma unroll 1
    for (int layer = 0; layer < 2; layer++) {
        const char* wcur = (layer == 0) ? w0base : w1base;
        const float* bias = (layer == 0) ? (b0 + p * 512) : (b1 + p * 512);
        const float* w2g  = W2 + p * 512;

#pragma unroll 1
        for (int q = 0; q < 2; q++) {
            int nch = (q + swap) & 1;    // which N half this group computes
            int gb = nch * 16;

            float acc[4][8][4];
#pragma unroll
            for (int mf = 0; mf < 4; mf++)
#pragma unroll
                for (int nf = 0; nf < 8; nf++)
#pragma unroll
                    for (int u = 0; u < 4; u++) acc[mf][nf][u] = 0.f;

            if (q == 0) {
                int gb2 = (1 - nch) * 16;   // next group's chunks
#pragma unroll 1
                for (int i = 0; i < 16; i++) {
                    int inext = i + 2;
                    int gnxt = (inext < 16) ? (gb + inext) : (gb2 + inext - 16);
                    issue_b(bw_base, wcur, inext % 3, gnxt, lseed, ldst);
                    cp_wait<2>();
                    __syncwarp();
                    compute_chunk(acc, sb, bw_base + (uint32_t)(i % 3) * BBUF,
                                  aoff, boff, i);
                }
            } else {
#pragma unroll 1
                for (int i = 0; i < 14; i++) {
                    int spos = 16 + i;
                    issue_b(bw_base, wcur, (spos + 2) % 3, gb + i + 2, lseed, ldst);
                    cp_wait<2>();
                    __syncwarp();
                    compute_chunk(acc, sb, bw_base + (uint32_t)(spos % 3) * BBUF,
                                  aoff, boff, i);
                }
                cp_wait<1>(); __syncwarp();
                compute_chunk(acc, sb, bw_base + (uint32_t)(30 % 3) * BBUF, aoff, boff, 14);
                cp_wait<0>(); __syncwarp();
                compute_chunk(acc, sb, bw_base + (uint32_t)(31 % 3) * BBUF, aoff, boff, 15);
            }

            // Epilogues
            if (layer == 0 && q == 0) {
                // first-computed half -> g_h (compact 256-col)
#pragma unroll
                for (int mf = 0; mf < 4; mf++) {
                    size_t r0 = (size_t)(p * NTOT) + m0 + mf * 16 + (lane >> 2);
#pragma unroll
                    for (int nf = 0; nf < 8; nf++) {
                        int cl = wn * 64 + nf * 8 + (lane & 3) * 2;
                        float2 bv = *(const float2*)(bias + nch * 256 + cl);
                        float* c4 = acc[mf][nf];
                        __half2 h0 = __floats2half2_rn(fmaxf(c4[0] + bv.x, 0.f),
                                                       fmaxf(c4[1] + bv.y, 0.f));
                        __half2 h1 = __floats2half2_rn(fmaxf(c4[2] + bv.x, 0.f),
                                                       fmaxf(c4[3] + bv.y, 0.f));
                        *(__half2*)(g_h + r0 * 256 + cl) = h0;
                        *(__half2*)(g_h + (r0 + 8) * 256 + cl) = h1;
                    }
                }
            } else if (layer == 0) {
                // Transition: reload first half from g_h; STS second half into A;
                // prime layer-1 pipeline (its first group = swap order again)
                int nch_f = 1 - nch;     // first-computed half (staged in g_h)
                __syncthreads();         // all warps done reading A (e tile)
                for (int i = tid; i < 64 * 32; i += THREADS) {
                    int row = i >> 5, c = i & 31;
                    int ca = nch_f * 32 + c;
                    cp16(sb + (uint32_t)row * 1024 + (uint32_t)((ca ^ (row & 7)) << 4),
                         g_h + ((size_t)(p * NTOT) + m0 + row) * 256 + c * 8);
                }
                cp_commit();
                {
                    int g0 = swap * 16;
                    issue_b(bw_base, w1base, 0, g0,     lseed, ldst);
                    issue_b(bw_base, w1base, 1, g0 + 1, lseed, ldst);
                }
                // STS second half directly into A (overlaps cp.async latency)
#pragma unroll
                for (int mf = 0; mf < 4; mf++) {
                    int r = mf * 16 + (lane >> 2);
#pragma unroll
                    for (int nf = 0; nf < 8; nf++) {
                        int col = nch * 256 + wn * 64 + nf * 8 + (lane & 3) * 2;
                        float2 bv = *(const float2*)(bias + col);
                        float* c4 = acc[mf][nf];
                        __half2 h0 = __floats2half2_rn(fmaxf(c4[0] + bv.x, 0.f),
                                                       fmaxf(c4[1] + bv.y, 0.f));
                        __half2 h1 = __floats2half2_rn(fmaxf(c4[2] + bv.x, 0.f),
                                                       fmaxf(c4[3] + bv.y, 0.f));
                        int ca = col >> 3;
                        uint32_t off = (uint32_t)r * 1024 +
                                       (uint32_t)((ca ^ (r & 7)) << 4) +
                                       (uint32_t)(lane & 3) * 4;
                        *(__half2*)(smem + off) = h0;
                        *(__half2*)(smem + off + 8192) = h1;   // row+8: same swizzle phase
                    }
                }
                cp_wait<2>();   // A reload landed (layer-1 B0/B1 may be pending)
                __syncthreads();
            } else {
                // layer 1: fold into layer-2 dot
#pragma unroll
                for (int mf = 0; mf < 4; mf++) {
#pragma unroll
                    for (int nf = 0; nf < 8; nf++) {
                        int col = nch * 256 + wn * 64 + nf * 8 + (lane & 3) * 2;
                        float2 bv = *(const float2*)(bias + col);
                        float2 wv = *(const float2*)(w2g + col);
                        float* c4 = acc[mf][nf];
                        pacc[mf][0] = fmaf(fmaxf(c4[0] + bv.x, 0.f), wv.x,
                                      fmaf(fmaxf(c4[1] + bv.y, 0.f), wv.y, pacc[mf][0]));
                        pacc[mf][1] = fmaf(fmaxf(c4[2] + bv.x, 0.f), wv.x,
                                      fmaf(fmaxf(c4[3] + bv.y, 0.f), wv.y, pacc[mf][1]));
                    }
                }
            }
        }
    }

    // Final reduction (scratch reuses B region)
    __syncthreads();
    float* red = (float*)(smem + SB);
#pragma unroll
    for (int mf = 0; mf < 4; mf++)
#pragma unroll
        for (int rp = 0; rp < 2; rp++) {
            float v = pacc[mf][rp];
            v += __shfl_xor_sync(0xffffffffu, v, 1);
            v += __shfl_xor_sync(0xffffffffu, v, 2);
            if ((lane & 3) == 0) {
                int row = mf * 16 + rp * 8 + (lane >> 2);
                red[row * 4 + wn] = v;
            }
        }
    __syncthreads();
    if (tid < MT) {
        float z = red[tid * 4] + red[tid * 4 + 1] + red[tid * 4 + 2] + red[tid * 4 + 3] + b2[p];
        out[((size_t)(m0 + tid)) * PP + p] = 1.f / (1.f + __expf(-z));
    }
}

// ---------------------------------------------------------------------------
// Launch
// ---------------------------------------------------------------------------
extern "C" void kernel_launch(void* const* d_in, const int* in_sizes, int n_in,
                              void* d_out, int out_size) {
    const float* e  = (const float*)d_in[0];
    const float* W0 = (const float*)d_in[1];
    const float* b0 = (const float*)d_in[2];
    const float* W1 = (const float*)d_in[3];
    const float* b1 = (const float*)d_in[4];
    const float* W2 = (const float*)d_in[5];
    const float* b2 = (const float*)d_in[6];
    float* out = (float*)d_out;

    cudaFuncSetAttribute(mlp_fused, cudaFuncAttributeMaxDynamicSharedMemorySize, SMEM_BYTES);

    conv_w_kernel<<<dim3(16, 16, 32), dim3(32, 8)>>>(W0, W1);
    mlp_fused<<<PP * (NTOT / MT), THREADS, SMEM_BYTES>>>(e, b0, b1, W2, b2, out);
}

// round 13
// speedup vs baseline: 1.0057x; 1.0057x over previous
#include <cuda_runtime.h>
#include <cuda_fp16.h>
#include <cstdint>
#include <math.h>

// Problem constants
#define PP    16
#define EE    512
#define HH    512
#define NTOT  8192

// Tiling: 2 CTAs/SM; warp-private 3-stage B pipeline; swizzled smem
#define MT       64
#define THREADS  128   // 4 warps: warp tile 64x64

#define SA     0                 // A: 64 rows x 1024B, XOR-swizzled
#define SB     65536             // B: 4 warps x 3 bufs x 4096B
#define BBUF   4096
#define BWARP  (3 * BBUF)
#define SMEM_BYTES 114688        // -> 2 CTAs/SM

// Static device scratch
// Pipeline-order weights: [p][g=0..31][row 0..255][k 0..31] halves
__device__ __align__(16) __half g_w0t[(size_t)PP * HH * EE];
__device__ __align__(16) __half g_w1t[(size_t)PP * HH * HH];
__device__ __align__(16) __half g_h[(size_t)PP * NTOT * 256];  // low half staged

// ---------------------------------------------------------------------------
// Base-ISA PTX helpers
// ---------------------------------------------------------------------------
__device__ __forceinline__ uint32_t smem_u32(const void* p) {
    uint32_t a;
    asm("{ .reg .u64 t; cvta.to.shared.u64 t, %1; cvt.u32.u64 %0, t; }"
        : "=r"(a) : "l"(p));
    return a;
}
__device__ __forceinline__ void cp16(uint32_t dst, const void* src) {
    asm volatile("cp.async.cg.shared.global [%0], [%1], 16;" :: "r"(dst), "l"(src));
}
__device__ __forceinline__ void cp_commit() { asm volatile("cp.async.commit_group;" ::: "memory"); }
template <int N>
__device__ __forceinline__ void cp_wait() { asm volatile("cp.async.wait_group %0;" :: "n"(N) : "memory"); }

__device__ __forceinline__ void ldm4(uint32_t* r, uint32_t a) {
    asm volatile("ldmatrix.sync.aligned.m8n8.x4.shared.b16 {%0,%1,%2,%3}, [%4];"
                 : "=r"(r[0]), "=r"(r[1]), "=r"(r[2]), "=r"(r[3]) : "r"(a));
}
__device__ __forceinline__ void mma16816(float* c, const uint32_t* a, const uint32_t* b) {
    asm volatile(
        "mma.sync.aligned.m16n8k16.row.col.f32.f16.f16.f32 "
        "{%0,%1,%2,%3}, {%4,%5,%6,%7}, {%8,%9}, {%0,%1,%2,%3};"
        : "+f"(c[0]), "+f"(c[1]), "+f"(c[2]), "+f"(c[3])
        : "r"(a[0]), "r"(a[1]), "r"(a[2]), "r"(a[3]), "r"(b[0]), "r"(b[1]));
}

// Issue one warp-private B chunk g (0..31), contiguous 4KB slab per warp
__device__ __forceinline__ void issue_b_chunk(uint32_t bw_base, const char* wbase,
                                              int g, uint32_t lseed, uint32_t ldst) {
    uint32_t bdst = bw_base + (uint32_t)(g % 3) * BBUF + ldst;
    const char* src = wbase + (size_t)g * 16384 + lseed;
#pragma unroll
    for (int it = 0; it < 8; it++)
        cp16(bdst + it * 512, src + it * 512);
    cp_commit();
}

// One K-chunk of MMAs (64 HMMA) against buffer g
__device__ __forceinline__ void compute_chunk(float (*acc)[8][4], uint32_t sbA,
                                              uint32_t bbase, const uint32_t* aoff,
                                              const uint32_t* boff, int kc) {
#pragma unroll
    for (int ks = 0; ks < 2; ks++) {
        uint32_t kbits = ((uint32_t)kc << 6) ^ ((uint32_t)ks << 5);
        uint32_t aR[4][4];
#pragma unroll
        for (int mf = 0; mf < 4; mf++)
            ldm4(aR[mf], sbA + (aoff[mf] ^ kbits));
        uint32_t bR[4][4];
#pragma unroll
        for (int nf2 = 0; nf2 < 4; nf2++)
            ldm4(bR[nf2], bbase + (boff[nf2] ^ ((uint32_t)ks << 5)));
#pragma unroll
        for (int mf = 0; mf < 4; mf++)
#pragma unroll
            for (int nf = 0; nf < 8; nf++)
                mma16816(acc[mf][nf], aR[mf], &bR[nf >> 1][(nf & 1) * 2]);
    }
}

// ---------------------------------------------------------------------------
// Pre-pass: both weights, one launch. W [p][kin][cout] fp32 -> Wt[p][g][n][k]
//   g = (cout/256)*16 + kin/32, n = cout%256, k = kin%32
// ---------------------------------------------------------------------------
__global__ void conv_w_kernel(const float* __restrict__ W0f,
                              const float* __restrict__ W1f) {
    __shared__ float tile[32][33];
    int which = blockIdx.z >> 4;
    int p = blockIdx.z & 15;
    const float* w = (which ? W1f : W0f) + (size_t)p * 512 * 512;
    __half* wt = (which ? g_w1t : g_w0t) + (size_t)p * 512 * 512;
    int c0 = blockIdx.x * 32;   // cout tile
    int r0 = blockIdx.y * 32;   // kin tile
    for (int j = threadIdx.y; j < 32; j += 8)
        tile[j][threadIdx.x] = w[(size_t)(r0 + j) * 512 + c0 + threadIdx.x];
    __syncthreads();
    int g = (c0 >> 8) * 16 + (r0 >> 5);
    int nloc = c0 & 255;
    for (int jj = threadIdx.y; jj < 32; jj += 8)
        wt[((size_t)g * 256 + nloc + jj) * 32 + threadIdx.x] =
            __float2half(tile[threadIdx.x][jj]);
}

// ---------------------------------------------------------------------------
// Fused MLP: 4 warps, 64x64 warp tiles, warp-private 3-stage B pipeline
// ---------------------------------------------------------------------------
__global__ void __launch_bounds__(THREADS, 2)
mlp_fused(const float* __restrict__ e,
          const float* __restrict__ b0, const float* __restrict__ b1,
          const float* __restrict__ W2, const float* __restrict__ b2,
          float* __restrict__ out) {
    extern __shared__ char smem[];
    uint32_t sb = smem_u32(smem);
    int tid = threadIdx.x;
    int lane = tid & 31, wid = tid >> 5;
    int wn = wid;
    int p = blockIdx.x >> 7;
    int mt = blockIdx.x & 127;
    int m0 = mt * MT;

    // lane constants
    int selA = lane >> 3;
    int a_row  = (selA & 1) * 8 + (lane & 7);
    int a_koff = (selA >> 1);
    int b_row  = (lane >> 4) * 8 + (lane & 7);
    int b_kchk = (lane >> 3) & 1;

    uint32_t aoff[4], boff[4];
#pragma unroll
    for (int mf = 0; mf < 4; mf++) {
        int row = mf * 16 + a_row;
        aoff[mf] = (uint32_t)row * 1024 + (uint32_t)(((row & 7) ^ a_koff) << 4);
    }
#pragma unroll
    for (int nf2 = 0; nf2 < 4; nf2++) {
        int n = nf2 * 16 + b_row;
        boff[nf2] = (uint32_t)n * 64 + (uint32_t)((((n >> 1) & 3) ^ b_kchk) << 4);
    }

    uint32_t bw_base = sb + SB + (uint32_t)wn * BWARP;
    uint32_t lseed = (uint32_t)wn * 4096 + (uint32_t)(lane >> 2) * 64 + (uint32_t)(lane & 3) * 16;
    uint32_t ldst  = (uint32_t)(lane >> 2) * 64 +
                     (uint32_t)(((lane & 3) ^ ((lane >> 3) & 3)) << 4);

    const char* w0base = (const char*)(g_w0t + (size_t)p * 512 * 512);
    const char* w1base = (const char*)(g_w1t + (size_t)p * 512 * 512);

    // Prologue: layer-0 B0/B1 prefetch first, then e fp32->fp16 directly into A
    issue_b_chunk(bw_base, w0base, 0, lseed, ldst);
    issue_b_chunk(bw_base, w0base, 1, lseed, ldst);
#pragma unroll 4
    for (int i = tid; i < 64 * 64; i += THREADS) {   // 4096 x 16B chunks
        int row = i >> 6, c = i & 63;
        const float4* s4 = (const float4*)(e + (size_t)(m0 + row) * 512 + c * 8);
        float4 v0 = s4[0], v1 = s4[1];
        __half2 h0 = __floats2half2_rn(v0.x, v0.y);
        __half2 h1 = __floats2half2_rn(v0.z, v0.w);
        __half2 h2 = __floats2half2_rn(v1.x, v1.y);
        __half2 h3 = __floats2half2_rn(v1.z, v1.w);
        uint4 pk;
        pk.x = *(uint32_t*)&h0; pk.y = *(uint32_t*)&h1;
        pk.z = *(uint32_t*)&h2; pk.w = *(uint32_t*)&h3;
        *(uint4*)(smem + (uint32_t)row * 1024 + (uint32_t)((c ^ (row & 7)) << 4)) = pk;
    }
    __syncthreads();

    float pacc[4][2] = {{0.f,0.f},{0.f,0.f},{0.f,0.f},{0.f,0.f}};

#pragma unroll 1
    for (int layer = 0; layer < 2; layer++) {
        const char* wcur = (layer == 0) ? w0base : w1base;
        const float* bias = (layer == 0) ? (b0 + p * 512) : (b1 + p * 512);
        const float* w2g  = W2 + p * 512;

#pragma unroll 1
        for (int nch = 0; nch < 2; nch++) {
            float acc[4][8][4];
#pragma unroll
            for (int mf = 0; mf < 4; mf++)
#pragma unroll
                for (int nf = 0; nf < 8; nf++)
#pragma unroll
                    for (int u = 0; u < 4; u++) acc[mf][nf][u] = 0.f;

            if (nch == 0) {
                // steady state: always issue g+2, constant wait depth
#pragma unroll 1
                for (int kc = 0; kc < 16; kc++) {
                    issue_b_chunk(bw_base, wcur, kc + 2, lseed, ldst);
                    cp_wait<2>();
                    __syncwarp();
                    compute_chunk(acc, sb, bw_base + (uint32_t)(kc % 3) * BBUF,
                                  aoff, boff, kc);
                }
            } else {
#pragma unroll 1
                for (int kc = 0; kc < 14; kc++) {
                    issue_b_chunk(bw_base, wcur, kc + 18, lseed, ldst);
                    cp_wait<2>();
                    __syncwarp();
                    compute_chunk(acc, sb, bw_base + (uint32_t)((kc + 16) % 3) * BBUF,
                                  aoff, boff, kc);
                }
                cp_wait<1>(); __syncwarp();
                compute_chunk(acc, sb, bw_base + (uint32_t)(30 % 3) * BBUF, aoff, boff, 14);
                cp_wait<0>(); __syncwarp();
                compute_chunk(acc, sb, bw_base + (uint32_t)(31 % 3) * BBUF, aoff, boff, 15);
            }

            // Epilogues
            if (layer == 0 && nch == 0) {
#pragma unroll
                for (int mf = 0; mf < 4; mf++) {
                    size_t r0 = (size_t)(p * NTOT) + m0 + mf * 16 + (lane >> 2);
#pragma unroll
                    for (int nf = 0; nf < 8; nf++) {
                        int col = wn * 64 + nf * 8 + (lane & 3) * 2;
                        float2 bv = *(const float2*)(bias + col);
                        float* c4 = acc[mf][nf];
                        __half2 h0 = __floats2half2_rn(fmaxf(c4[0] + bv.x, 0.f),
                                                       fmaxf(c4[1] + bv.y, 0.f));
                        __half2 h1 = __floats2half2_rn(fmaxf(c4[2] + bv.x, 0.f),
                                                       fmaxf(c4[3] + bv.y, 0.f));
                        *(__half2*)(g_h + r0 * 256 + col) = h0;
                        *(__half2*)(g_h + (r0 + 8) * 256 + col) = h1;
                    }
                }
            } else if (layer == 0) {
                // Transition: STS h cols 256..511 into A; reload cols 0..255; prime layer-1 B
                __syncthreads();
                for (int i = tid; i < 64 * 32; i += THREADS) {
                    int row = i >> 5, c = i & 31;
                    uint32_t cph = (uint32_t)(c ^ (row & 7));
                    cp16(sb + (uint32_t)row * 1024 + cph * 16,
                         g_h + ((size_t)(p * NTOT) + m0 + row) * 256 + c * 8);
                }
                cp_commit();
                issue_b_chunk(bw_base, w1base, 0, lseed, ldst);
                issue_b_chunk(bw_base, w1base, 1, lseed, ldst);
#pragma unroll
                for (int mf = 0; mf < 4; mf++) {
                    int r = mf * 16 + (lane >> 2);
#pragma unroll
                    for (int nf = 0; nf < 8; nf++) {
                        int col = 256 + wn * 64 + nf * 8 + (lane & 3) * 2;
                        float2 bv = *(const float2*)(bias + col);
                        float* c4 = acc[mf][nf];
                        __half2 h0 = __floats2half2_rn(fmaxf(c4[0] + bv.x, 0.f),
                                                       fmaxf(c4[1] + bv.y, 0.f));
                        __half2 h1 = __floats2half2_rn(fmaxf(c4[2] + bv.x, 0.f),
                                                       fmaxf(c4[3] + bv.y, 0.f));
                        int ca = col >> 3;
                        uint32_t off = (uint32_t)r * 1024 +
                                       (uint32_t)((ca ^ (r & 7)) << 4) +
                                       (uint32_t)(lane & 3) * 4;
                        *(__half2*)(smem + off) = h0;
                        *(__half2*)(smem + off + 8192) = h1;   // row+8: same swizzle phase
                    }
                }
                cp_wait<2>();     // A reload landed
                __syncthreads();
            } else {
                // layer 1: fold into layer-2 dot
#pragma unroll
                for (int mf = 0; mf < 4; mf++) {
#pragma unroll
                    for (int nf = 0; nf < 8; nf++) {
                        int col = nch * 256 + wn * 64 + nf * 8 + (lane & 3) * 2;
                        float2 bv = *(const float2*)(bias + col);
                        float2 wv = *(const float2*)(w2g + col);
                        float* c4 = acc[mf][nf];
                        pacc[mf][0] = fmaf(fmaxf(c4[0] + bv.x, 0.f), wv.x,
                                      fmaf(fmaxf(c4[1] + bv.y, 0.f), wv.y, pacc[mf][0]));
                        pacc[mf][1] = fmaf(fmaxf(c4[2] + bv.x, 0.f), wv.x,
                                      fmaf(fmaxf(c4[3] + bv.y, 0.f), wv.y, pacc[mf][1]));
                    }
                }
            }
        }
    }

    // Final reduction (scratch reuses B region)
    __syncthreads();
    float* red = (float*)(smem + SB);
#pragma unroll
    for (int mf = 0; mf < 4; mf++)
#pragma unroll
        for (int rp = 0; rp < 2; rp++) {
            float v = pacc[mf][rp];
            v += __shfl_xor_sync(0xffffffffu, v, 1);
            v += __shfl_xor_sync(0xffffffffu, v, 2);
            if ((lane & 3) == 0) {
                int row = mf * 16 + rp * 8 + (lane >> 2);
                red[row * 4 + wn] = v;
            }
        }
    __syncthreads();
    if (tid < MT) {
        float z = red[tid * 4] + red[tid * 4 + 1] + red[tid * 4 + 2] + red[tid * 4 + 3] + b2[p];
        out[((size_t)(m0 + tid)) * PP + p] = 1.f / (1.f + __expf(-z));
    }
}

// ---------------------------------------------------------------------------
// Launch
// ---------------------------------------------------------------------------
extern "C" void kernel_launch(void* const* d_in, const int* in_sizes, int n_in,
                              void* d_out, int out_size) {
    const float* e  = (const float*)d_in[0];
    const float* W0 = (const float*)d_in[1];
    const float* b0 = (const float*)d_in[2];
    const float* W1 = (const float*)d_in[3];
    const float* b1 = (const float*)d_in[4];
    const float* W2 = (const float*)d_in[5];
    const float* b2 = (const float*)d_in[6];
    float* out = (float*)d_out;

    cudaFuncSetAttribute(mlp_fused, cudaFuncAttributeMaxDynamicSharedMemorySize, SMEM_BYTES);

    conv_w_kernel<<<dim3(16, 16, 32), dim3(32, 8)>>>(W0, W1);
    mlp_fused<<<PP * (NTOT / MT), THREADS, SMEM_BYTES>>>(e, b0, b1, W2, b2, out);
}

// round 14
// speedup vs baseline: 1.0113x; 1.0056x over previous
#include <cuda_runtime.h>
#include <cuda_fp16.h>
#include <cstdint>
#include <math.h>

// Problem constants
#define PP    16
#define EE    512
#define HH    512
#define NTOT  8192

// Tiling: 2 CTAs/SM; warp-private 3-stage B pipeline; swizzled smem
#define MT       64
#define THREADS  128   // 4 warps: warp tile 64x64

#define SA     0                 // A: 64 rows x 1024B, XOR-swizzled
#define SB     65536             // B: 4 warps x 3 bufs x 4096B
#define BBUF   4096
#define BWARP  (3 * BBUF)
#define SMEM_BYTES 114688        // -> 2 CTAs/SM

// Static device scratch
__device__ __align__(16) __half g_e[(size_t)NTOT * EE];        // e, fp16
// Pipeline-order weights: [p][g=0..31][row 0..255][k 0..31] halves
__device__ __align__(16) __half g_w0t[(size_t)PP * HH * EE];
__device__ __align__(16) __half g_w1t[(size_t)PP * HH * HH];
__device__ __align__(16) __half g_h[(size_t)PP * NTOT * 256];  // low half staged

// ---------------------------------------------------------------------------
// Base-ISA PTX helpers
// ---------------------------------------------------------------------------
__device__ __forceinline__ uint32_t smem_u32(const void* p) {
    uint32_t a;
    asm("{ .reg .u64 t; cvta.to.shared.u64 t, %1; cvt.u32.u64 %0, t; }"
        : "=r"(a) : "l"(p));
    return a;
}
__device__ __forceinline__ void cp16(uint32_t dst, const void* src) {
    asm volatile("cp.async.cg.shared.global [%0], [%1], 16;" :: "r"(dst), "l"(src));
}
__device__ __forceinline__ void cp_commit() { asm volatile("cp.async.commit_group;" ::: "memory"); }
template <int N>
__device__ __forceinline__ void cp_wait() { asm volatile("cp.async.wait_group %0;" :: "n"(N) : "memory"); }

__device__ __forceinline__ void ldm4(uint32_t* r, uint32_t a) {
    asm volatile("ldmatrix.sync.aligned.m8n8.x4.shared.b16 {%0,%1,%2,%3}, [%4];"
                 : "=r"(r[0]), "=r"(r[1]), "=r"(r[2]), "=r"(r[3]) : "r"(a));
}
__device__ __forceinline__ void mma16816(float* c, const uint32_t* a, const uint32_t* b) {
    asm volatile(
        "mma.sync.aligned.m16n8k16.row.col.f32.f16.f16.f32 "
        "{%0,%1,%2,%3}, {%4,%5,%6,%7}, {%8,%9}, {%0,%1,%2,%3};"
        : "+f"(c[0]), "+f"(c[1]), "+f"(c[2]), "+f"(c[3])
        : "r"(a[0]), "r"(a[1]), "r"(a[2]), "r"(a[3]), "r"(b[0]), "r"(b[1]));
}

// Issue one warp-private B chunk g (0..31), contiguous 4KB slab per warp
__device__ __forceinline__ void issue_b_chunk(uint32_t bw_base, const char* wbase,
                                              int g, uint32_t lseed, uint32_t ldst) {
    uint32_t bdst = bw_base + (uint32_t)(g % 3) * BBUF + ldst;
    const char* src = wbase + (size_t)g * 16384 + lseed;
#pragma unroll
    for (int it = 0; it < 8; it++)
        cp16(bdst + it * 512, src + it * 512);
    cp_commit();
}

// One K-chunk of MMAs (64 HMMA) against buffer g
__device__ __forceinline__ void compute_chunk(float (*acc)[8][4], uint32_t sbA,
                                              uint32_t bbase, const uint32_t* aoff,
                                              const uint32_t* boff, int kc) {
#pragma unroll
    for (int ks = 0; ks < 2; ks++) {
        uint32_t kbits = ((uint32_t)kc << 6) ^ ((uint32_t)ks << 5);
        uint32_t aR[4][4];
#pragma unroll
        for (int mf = 0; mf < 4; mf++)
            ldm4(aR[mf], sbA + (aoff[mf] ^ kbits));
        uint32_t bR[4][4];
#pragma unroll
        for (int nf2 = 0; nf2 < 4; nf2++)
            ldm4(bR[nf2], bbase + (boff[nf2] ^ ((uint32_t)ks << 5)));
#pragma unroll
        for (int mf = 0; mf < 4; mf++)
#pragma unroll
            for (int nf = 0; nf < 8; nf++)
                mma16816(acc[mf][nf], aR[mf], &bR[nf >> 1][(nf & 1) * 2]);
    }
}

// ---------------------------------------------------------------------------
// Single fused pre-pass: z=0..31 weight transpose tiles; z=32..33 e-convert
//   Weights: W [p][kin][cout] fp32 -> Wt[p][g][n][k] fp16,
//     g = (cout/256)*16 + kin/32, n = cout%256, k = kin%32
// ---------------------------------------------------------------------------
__global__ void prepass_kernel(const float* __restrict__ e,
                               const float* __restrict__ W0f,
                               const float* __restrict__ W1f) {
    __shared__ float tile[32][33];
    if (blockIdx.z < 32) {
        int which = blockIdx.z >> 4;
        int p = blockIdx.z & 15;
        const float* w = (which ? W1f : W0f) + (size_t)p * 512 * 512;
        __half* wt = (which ? g_w1t : g_w0t) + (size_t)p * 512 * 512;
        int c0 = blockIdx.x * 32;   // cout tile
        int r0 = blockIdx.y * 32;   // kin tile
        for (int j = threadIdx.y; j < 32; j += 8)
            tile[j][threadIdx.x] = w[(size_t)(r0 + j) * 512 + c0 + threadIdx.x];
        __syncthreads();
        int g = (c0 >> 8) * 16 + (r0 >> 5);
        int nloc = c0 & 255;
        for (int jj = threadIdx.y; jj < 32; jj += 8)
            wt[((size_t)g * 256 + nloc + jj) * 32 + threadIdx.x] =
                __float2half(tile[threadIdx.x][jj]);
    } else {
        // e fp32 -> fp16: 512 blocks x 256 thr x 8 float4 = 4.19M floats
        int b = (blockIdx.z - 32) * 256 + blockIdx.y * 16 + blockIdx.x;
        int t = b * 256 + threadIdx.y * 32 + threadIdx.x;
#pragma unroll
        for (int k = 0; k < 8; k++) {
            int i = t * 8 + k;
            float4 v = ((const float4*)e)[i];
            __half2 a = __floats2half2_rn(v.x, v.y);
            __half2 bb = __floats2half2_rn(v.z, v.w);
            uint2 pk;
            pk.x = *(uint32_t*)&a;
            pk.y = *(uint32_t*)&bb;
            ((uint2*)g_e)[i] = pk;
        }
    }
}

// ---------------------------------------------------------------------------
// Fused MLP: 4 warps, 64x64 warp tiles, warp-private 3-stage B pipeline (R11)
// ---------------------------------------------------------------------------
__global__ void __launch_bounds__(THREADS, 2)
mlp_fused(const float* __restrict__ b0, const float* __restrict__ b1,
          const float* __restrict__ W2, const float* __restrict__ b2,
          float* __restrict__ out) {
    extern __shared__ char smem[];
    uint32_t sb = smem_u32(smem);
    int tid = threadIdx.x;
    int lane = tid & 31, wid = tid >> 5;
    int wn = wid;
    int p = blockIdx.x >> 7;
    int mt = blockIdx.x & 127;
    int m0 = mt * MT;

    // lane constants
    int selA = lane >> 3;
    int a_row  = (selA & 1) * 8 + (lane & 7);
    int a_koff = (selA >> 1);
    int b_row  = (lane >> 4) * 8 + (lane & 7);
    int b_kchk = (lane >> 3) & 1;

    uint32_t aoff[4], boff[4];
#pragma unroll
    for (int mf = 0; mf < 4; mf++) {
        int row = mf * 16 + a_row;
        aoff[mf] = (uint32_t)row * 1024 + (uint32_t)(((row & 7) ^ a_koff) << 4);
    }
#pragma unroll
    for (int nf2 = 0; nf2 < 4; nf2++) {
        int n = nf2 * 16 + b_row;
        boff[nf2] = (uint32_t)n * 64 + (uint32_t)((((n >> 1) & 3) ^ b_kchk) << 4);
    }

    uint32_t bw_base = sb + SB + (uint32_t)wn * BWARP;
    uint32_t lseed = (uint32_t)wn * 4096 + (uint32_t)(lane >> 2) * 64 + (uint32_t)(lane & 3) * 16;
    uint32_t ldst  = (uint32_t)(lane >> 2) * 64 +
                     (uint32_t)(((lane & 3) ^ ((lane >> 3) & 3)) << 4);

    const char* w0base = (const char*)(g_w0t + (size_t)p * 512 * 512);
    const char* w1base = (const char*)(g_w1t + (size_t)p * 512 * 512);

    // Prologue: A-tile cp (1 group), then layer-0 B0/B1 -- overlapped
    for (int i = tid; i < MT * 64; i += THREADS) {
        int row = i >> 6, c = i & 63;
        uint32_t cph = (uint32_t)(c ^ (row & 7));
        cp16(sb + (uint32_t)row * 1024 + cph * 16,
             g_e + ((size_t)(m0 + row)) * EE + c * 8);
    }
    cp_commit();
    issue_b_chunk(bw_base, w0base, 0, lseed, ldst);
    issue_b_chunk(bw_base, w0base, 1, lseed, ldst);
    cp_wait<2>();     // A landed; B0/B1 may still be in flight
    __syncthreads();

    float pacc[4][2] = {{0.f,0.f},{0.f,0.f},{0.f,0.f},{0.f,0.f}};

#pragma unroll 1
    for (int layer = 0; layer < 2; layer++) {
        const char* wcur = (layer == 0) ? w0base : w1base;
        const float* bias = (layer == 0) ? (b0 + p * 512) : (b1 + p * 512);
        const float* w2g  = W2 + p * 512;

#pragma unroll 1
        for (int nch = 0; nch < 2; nch++) {
            float acc[4][8][4];
#pragma unroll
            for (int mf = 0; mf < 4; mf++)
#pragma unroll
                for (int nf = 0; nf < 8; nf++)
#pragma unroll
                    for (int u = 0; u < 4; u++) acc[mf][nf][u] = 0.f;

            if (nch == 0) {
#pragma unroll 1
                for (int kc = 0; kc < 16; kc++) {
                    issue_b_chunk(bw_base, wcur, kc + 2, lseed, ldst);
                    cp_wait<2>();
                    __syncwarp();
                    compute_chunk(acc, sb, bw_base + (uint32_t)(kc % 3) * BBUF,
                                  aoff, boff, kc);
                }
            } else {
#pragma unroll 1
                for (int kc = 0; kc < 14; kc++) {
                    issue_b_chunk(bw_base, wcur, kc + 18, lseed, ldst);
                    cp_wait<2>();
                    __syncwarp();
                    compute_chunk(acc, sb, bw_base + (uint32_t)((kc + 16) % 3) * BBUF,
                                  aoff, boff, kc);
                }
                cp_wait<1>(); __syncwarp();
                compute_chunk(acc, sb, bw_base + (uint32_t)(30 % 3) * BBUF, aoff, boff, 14);
                cp_wait<0>(); __syncwarp();
                compute_chunk(acc, sb, bw_base + (uint32_t)(31 % 3) * BBUF, aoff, boff, 15);
            }

            // Epilogues
            if (layer == 0 && nch == 0) {
#pragma unroll
                for (int mf = 0; mf < 4; mf++) {
                    size_t r0 = (size_t)(p * NTOT) + m0 + mf * 16 + (lane >> 2);
#pragma unroll
                    for (int nf = 0; nf < 8; nf++) {
                        int col = wn * 64 + nf * 8 + (lane & 3) * 2;
                        float2 bv = *(const float2*)(bias + col);
                        float* c4 = acc[mf][nf];
                        __half2 h0 = __floats2half2_rn(fmaxf(c4[0] + bv.x, 0.f),
                                                       fmaxf(c4[1] + bv.y, 0.f));
                        __half2 h1 = __floats2half2_rn(fmaxf(c4[2] + bv.x, 0.f),
                                                       fmaxf(c4[3] + bv.y, 0.f));
                        *(__half2*)(g_h + r0 * 256 + col) = h0;
                        *(__half2*)(g_h + (r0 + 8) * 256 + col) = h1;
                    }
                }
            } else if (layer == 0) {
                // Transition: STS h cols 256..511 into A; reload cols 0..255; prime layer-1 B
                __syncthreads();
                for (int i = tid; i < 64 * 32; i += THREADS) {
                    int row = i >> 5, c = i & 31;
                    uint32_t cph = (uint32_t)(c ^ (row & 7));
                    cp16(sb + (uint32_t)row * 1024 + cph * 16,
                         g_h + ((size_t)(p * NTOT) + m0 + row) * 256 + c * 8);
                }
                cp_commit();
                issue_b_chunk(bw_base, w1base, 0, lseed, ldst);
                issue_b_chunk(bw_base, w1base, 1, lseed, ldst);
#pragma unroll
                for (int mf = 0; mf < 4; mf++) {
                    int r = mf * 16 + (lane >> 2);
#pragma unroll
                    for (int nf = 0; nf < 8; nf++) {
                        int col = 256 + wn * 64 + nf * 8 + (lane & 3) * 2;
                        float2 bv = *(const float2*)(bias + col);
                        float* c4 = acc[mf][nf];
                        __half2 h0 = __floats2half2_rn(fmaxf(c4[0] + bv.x, 0.f),
                                                       fmaxf(c4[1] + bv.y, 0.f));
                        __half2 h1 = __floats2half2_rn(fmaxf(c4[2] + bv.x, 0.f),
                                                       fmaxf(c4[3] + bv.y, 0.f));
                        int ca = col >> 3;
                        uint32_t off = (uint32_t)r * 1024 +
                                       (uint32_t)((ca ^ (r & 7)) << 4) +
                                       (uint32_t)(lane & 3) * 4;
                        *(__half2*)(smem + off) = h0;
                        *(__half2*)(smem + off + 8192) = h1;   // row+8: same swizzle phase
                    }
                }
                cp_wait<2>();     // A reload landed
                __syncthreads();
            } else {
                // layer 1: fold into layer-2 dot
#pragma unroll
                for (int mf = 0; mf < 4; mf++) {
#pragma unroll
                    for (int nf = 0; nf < 8; nf++) {
                        int col = nch * 256 + wn * 64 + nf * 8 + (lane & 3) * 2;
                        float2 bv = *(const float2*)(bias + col);
                        float2 wv = *(const float2*)(w2g + col);
                        float* c4 = acc[mf][nf];
                        pacc[mf][0] = fmaf(fmaxf(c4[0] + bv.x, 0.f), wv.x,
                                      fmaf(fmaxf(c4[1] + bv.y, 0.f), wv.y, pacc[mf][0]));
                        pacc[mf][1] = fmaf(fmaxf(c4[2] + bv.x, 0.f), wv.x,
                                      fmaf(fmaxf(c4[3] + bv.y, 0.f), wv.y, pacc[mf][1]));
                    }
                }
            }
        }
    }

    // Final reduction (scratch reuses B region)
    __syncthreads();
    float* red = (float*)(smem + SB);
#pragma unroll
    for (int mf = 0; mf < 4; mf++)
#pragma unroll
        for (int rp = 0; rp < 2; rp++) {
            float v = pacc[mf][rp];
            v += __shfl_xor_sync(0xffffffffu, v, 1);
            v += __shfl_xor_sync(0xffffffffu, v, 2);
            if ((lane & 3) == 0) {
                int row = mf * 16 + rp * 8 + (lane >> 2);
                red[row * 4 + wn] = v;
            }
        }
    __syncthreads();
    if (tid < MT) {
        float z = red[tid * 4] + red[tid * 4 + 1] + red[tid * 4 + 2] + red[tid * 4 + 3] + b2[p];
        out[((size_t)(m0 + tid)) * PP + p] = 1.f / (1.f + __expf(-z));
    }
}

// ---------------------------------------------------------------------------
// Launch
// ---------------------------------------------------------------------------
extern "C" void kernel_launch(void* const* d_in, const int* in_sizes, int n_in,
                              void* d_out, int out_size) {
    const float* e  = (const float*)d_in[0];
    const float* W0 = (const float*)d_in[1];
    const float* b0 = (const float*)d_in[2];
    const float* W1 = (const float*)d_in[3];
    const float* b1 = (const float*)d_in[4];
    const float* W2 = (const float*)d_in[5];
    const float* b2 = (const float*)d_in[6];
    float* out = (float*)d_out;

    cudaFuncSetAttribute(mlp_fused, cudaFuncAttributeMaxDynamicSharedMemorySize, SMEM_BYTES);

    prepass_kernel<<<dim3(16, 16, 34), dim3(32, 8)>>>(e, W0, W1);
    mlp_fused<<<PP * (NTOT / MT), THREADS, SMEM_BYTES>>>(b0, b1, W2, b2, out);
}

// round 16
// speedup vs baseline: 1.0439x; 1.0322x over previous
#include <cuda_runtime.h>
#include <cuda_fp16.h>
#include <cstdint>
#include <math.h>

// Problem constants
#define PP    16
#define EE    512
#define HH    512
#define NTOT  8192

// Tiling: 2 CTAs/SM; warp-private 3-stage B pipeline; swizzled smem
#define MT       64
#define THREADS  128   // 4 warps: warp tile 64x64

#define SA     0                 // A: 64 rows x 1024B, XOR-swizzled
#define SB     65536             // B: 4 warps x 3 bufs x 4096B
#define BBUF   4096
#define BWARP  (3 * BBUF)
#define SMEM_BYTES 114688        // -> 2 CTAs/SM

// Static device scratch
__device__ __align__(16) __half g_e[(size_t)NTOT * EE];        // e, fp16
// Pipeline-order weights: [p][g=0..31][row 0..255][k 0..31] halves
__device__ __align__(16) __half g_w0t[(size_t)PP * HH * EE];
__device__ __align__(16) __half g_w1t[(size_t)PP * HH * HH];
__device__ __align__(16) __half g_h[(size_t)PP * NTOT * 256];  // low half staged

// ---------------------------------------------------------------------------
// Base-ISA PTX helpers
// ---------------------------------------------------------------------------
__device__ __forceinline__ uint32_t smem_u32(const void* p) {
    uint32_t a;
    asm("{ .reg .u64 t; cvta.to.shared.u64 t, %1; cvt.u32.u64 %0, t; }"
        : "=r"(a) : "l"(p));
    return a;
}
__device__ __forceinline__ void cp16(uint32_t dst, const void* src) {
    asm volatile("cp.async.cg.shared.global [%0], [%1], 16;" :: "r"(dst), "l"(src));
}
__device__ __forceinline__ void cp_commit() { asm volatile("cp.async.commit_group;" ::: "memory"); }
template <int N>
__device__ __forceinline__ void cp_wait() { asm volatile("cp.async.wait_group %0;" :: "n"(N) : "memory"); }

__device__ __forceinline__ void ldm4(uint32_t* r, uint32_t a) {
    asm volatile("ldmatrix.sync.aligned.m8n8.x4.shared.b16 {%0,%1,%2,%3}, [%4];"
                 : "=r"(r[0]), "=r"(r[1]), "=r"(r[2]), "=r"(r[3]) : "r"(a));
}
__device__ __forceinline__ void mma16816(float* c, const uint32_t* a, const uint32_t* b) {
    asm volatile(
        "mma.sync.aligned.m16n8k16.row.col.f32.f16.f16.f32 "
        "{%0,%1,%2,%3}, {%4,%5,%6,%7}, {%8,%9}, {%0,%1,%2,%3};"
        : "+f"(c[0]), "+f"(c[1]), "+f"(c[2]), "+f"(c[3])
        : "r"(a[0]), "r"(a[1]), "r"(a[2]), "r"(a[3]), "r"(b[0]), "r"(b[1]));
}

// Issue one warp-private B chunk g (0..31), contiguous 4KB slab per warp
__device__ __forceinline__ void issue_b_chunk(uint32_t bw_base, const char* wbase,
                                              int g, uint32_t lseed, uint32_t ldst) {
    uint32_t bdst = bw_base + (uint32_t)(g % 3) * BBUF + ldst;
    const char* src = wbase + (size_t)g * 16384 + lseed;
#pragma unroll
    for (int it = 0; it < 8; it++)
        cp16(bdst + it * 512, src + it * 512);
    cp_commit();
}

// One K-chunk of MMAs (64 HMMA) against buffer g
__device__ __forceinline__ void compute_chunk(float (*acc)[8][4], uint32_t sbA,
                                              uint32_t bbase, const uint32_t* aoff,
                                              const uint32_t* boff, int kc) {
#pragma unroll
    for (int ks = 0; ks < 2; ks++) {
        uint32_t kbits = ((uint32_t)kc << 6) ^ ((uint32_t)ks << 5);
        uint32_t aR[4][4];
#pragma unroll
        for (int mf = 0; mf < 4; mf++)
            ldm4(aR[mf], sbA + (aoff[mf] ^ kbits));
        uint32_t bR[4][4];
#pragma unroll
        for (int nf2 = 0; nf2 < 4; nf2++)
            ldm4(bR[nf2], bbase + (boff[nf2] ^ ((uint32_t)ks << 5)));
#pragma unroll
        for (int mf = 0; mf < 4; mf++)
#pragma unroll
            for (int nf = 0; nf < 8; nf++)
                mma16816(acc[mf][nf], aR[mf], &bR[nf >> 1][(nf & 1) * 2]);
    }
}

// ---------------------------------------------------------------------------
// Single fused pre-pass.
//   z=0..1   : e fp32->fp16 (coalesced, heavy blocks scheduled FIRST)
//   z=2..33  : weight transpose tiles
//     W [p][kin][cout] fp32 -> Wt[p][g][n][k] fp16,
//     g = (cout/256)*16 + kin/32, n = cout%256, k = kin%32
// ---------------------------------------------------------------------------
__global__ void prepass_kernel(const float* __restrict__ e,
                               const float* __restrict__ W0f,
                               const float* __restrict__ W1f) {
    __shared__ float tile[32][33];
    if (blockIdx.z >= 2) {
        int zz = blockIdx.z - 2;
        int which = zz >> 4;
        int p = zz & 15;
        const float* w = (which ? W1f : W0f) + (size_t)p * 512 * 512;
        __half* wt = (which ? g_w1t : g_w0t) + (size_t)p * 512 * 512;
        int c0 = blockIdx.x * 32;   // cout tile
        int r0 = blockIdx.y * 32;   // kin tile
        for (int j = threadIdx.y; j < 32; j += 8)
            tile[j][threadIdx.x] = w[(size_t)(r0 + j) * 512 + c0 + threadIdx.x];
        __syncthreads();
        int g = (c0 >> 8) * 16 + (r0 >> 5);
        int nloc = c0 & 255;
        for (int jj = threadIdx.y; jj < 32; jj += 8)
            wt[((size_t)g * 256 + nloc + jj) * 32 + threadIdx.x] =
                __float2half(tile[threadIdx.x][jj]);
    } else {
        // e convert: 512 blocks x 256 thr x 8 float4, fully coalesced
        int b = blockIdx.z * 256 + blockIdx.y * 16 + blockIdx.x;
        int t = threadIdx.y * 32 + threadIdx.x;
        int base = b * 2048;          // float4 units; block covers 32KB contiguous
#pragma unroll
        for (int k = 0; k < 8; k++) {
            int i = base + k * 256 + t;
            float4 v = ((const float4*)e)[i];
            __half2 a = __floats2half2_rn(v.x, v.y);
            __half2 bb = __floats2half2_rn(v.z, v.w);
            uint2 pk;
            pk.x = *(uint32_t*)&a;
            pk.y = *(uint32_t*)&bb;
            ((uint2*)g_e)[i] = pk;
        }
    }
}

// ---------------------------------------------------------------------------
// Fused MLP: 4 warps, 64x64 warp tiles, warp-private 3-stage B pipeline
// ---------------------------------------------------------------------------
__global__ void __launch_bounds__(THREADS, 2)
mlp_fused(const float* __restrict__ b0, const float* __restrict__ b1,
          const float* __restrict__ W2, const float* __restrict__ b2,
          float* __restrict__ out) {
    extern __shared__ char smem[];
    uint32_t sb = smem_u32(smem);
    int tid = threadIdx.x;
    int lane = tid & 31, wid = tid >> 5;
    int wn = wid;
    int p = blockIdx.x >> 7;
    int mt = blockIdx.x & 127;
    int m0 = mt * MT;

    // lane constants
    int selA = lane >> 3;
    int a_row  = (selA & 1) * 8 + (lane & 7);
    int a_koff = (selA >> 1);
    int b_row  = (lane >> 4) * 8 + (lane & 7);
    int b_kchk = (lane >> 3) & 1;

    uint32_t aoff[4], boff[4];
#pragma unroll
    for (int mf = 0; mf < 4; mf++) {
        int row = mf * 16 + a_row;
        aoff[mf] = (uint32_t)row * 1024 + (uint32_t)(((row & 7) ^ a_koff) << 4);
    }
#pragma unroll
    for (int nf2 = 0; nf2 < 4; nf2++) {
        int n = nf2 * 16 + b_row;
        boff[nf2] = (uint32_t)n * 64 + (uint32_t)((((n >> 1) & 3) ^ b_kchk) << 4);
    }

    uint32_t bw_base = sb + SB + (uint32_t)wn * BWARP;
    uint32_t lseed = (uint32_t)wn * 4096 + (uint32_t)(lane >> 2) * 64 + (uint32_t)(lane & 3) * 16;
    uint32_t ldst  = (uint32_t)(lane >> 2) * 64 +
                     (uint32_t)(((lane & 3) ^ ((lane >> 3) & 3)) << 4);

    const char* w0base = (const char*)(g_w0t + (size_t)p * 512 * 512);
    const char* w1base = (const char*)(g_w1t + (size_t)p * 512 * 512);

    // Prologue: A-tile cp (1 group), then layer-0 B0/B1 -- overlapped
    for (int i = tid; i < MT * 64; i += THREADS) {
        int row = i >> 6, c = i & 63;
        uint32_t cph = (uint32_t)(c ^ (row & 7));
        cp16(sb + (uint32_t)row * 1024 + cph * 16,
             g_e + ((size_t)(m0 + row)) * EE + c * 8);
    }
    cp_commit();
    issue_b_chunk(bw_base, w0base, 0, lseed, ldst);
    issue_b_chunk(bw_base, w0base, 1, lseed, ldst);
    cp_wait<2>();     // A landed; B0/B1 may still be in flight
    __syncthreads();

    float pacc[4][2] = {{0.f,0.f},{0.f,0.f},{0.f,0.f},{0.f,0.f}};

#pragma unroll 1
    for (int layer = 0; layer < 2; layer++) {
        const char* wcur = (layer == 0) ? w0base : w1base;
        const float* bias = (layer == 0) ? (b0 + p * 512) : (b1 + p * 512);
        const float* w2g  = W2 + p * 512;

#pragma unroll 1
        for (int nch = 0; nch < 2; nch++) {
            float acc[4][8][4];
#pragma unroll
            for (int mf = 0; mf < 4; mf++)
#pragma unroll
                for (int nf = 0; nf < 8; nf++)
#pragma unroll
                    for (int u = 0; u < 4; u++) acc[mf][nf][u] = 0.f;

            if (nch == 0) {
#pragma unroll 1
                for (int kc = 0; kc < 16; kc++) {
                    issue_b_chunk(bw_base, wcur, kc + 2, lseed, ldst);
                    cp_wait<2>();
                    __syncwarp();
                    compute_chunk(acc, sb, bw_base + (uint32_t)(kc % 3) * BBUF,
                                  aoff, boff, kc);
                }
            } else {
#pragma unroll 1
                for (int kc = 0; kc < 14; kc++) {
                    issue_b_chunk(bw_base, wcur, kc + 18, lseed, ldst);
                    cp_wait<2>();
                    __syncwarp();
                    compute_chunk(acc, sb, bw_base + (uint32_t)((kc + 16) % 3) * BBUF,
                                  aoff, boff, kc);
                }
                cp_wait<1>(); __syncwarp();
                compute_chunk(acc, sb, bw_base + (uint32_t)(30 % 3) * BBUF, aoff, boff, 14);
                cp_wait<0>(); __syncwarp();
                compute_chunk(acc, sb, bw_base + (uint32_t)(31 % 3) * BBUF, aoff, boff, 15);
            }

            // Epilogues
            if (layer == 0 && nch == 0) {
#pragma unroll
                for (int mf = 0; mf < 4; mf++) {
                    size_t r0 = (size_t)(p * NTOT) + m0 + mf * 16 + (lane >> 2);
#pragma unroll
                    for (int nf = 0; nf < 8; nf++) {
                        int col = wn * 64 + nf * 8 + (lane & 3) * 2;
                        float2 bv = *(const float2*)(bias + col);
                        float* c4 = acc[mf][nf];
                        __half2 h0 = __floats2half2_rn(fmaxf(c4[0] + bv.x, 0.f),
                                                       fmaxf(c4[1] + bv.y, 0.f));
                        __half2 h1 = __floats2half2_rn(fmaxf(c4[2] + bv.x, 0.f),
                                                       fmaxf(c4[3] + bv.y, 0.f));
                        *(__half2*)(g_h + r0 * 256 + col) = h0;
                        *(__half2*)(g_h + (r0 + 8) * 256 + col) = h1;
                    }
                }
            } else if (layer == 0) {
                // Transition: STS h cols 256..511 into A; reload cols 0..255; prime layer-1 B
                __syncthreads();
                for (int i = tid; i < 64 * 32; i += THREADS) {
                    int row = i >> 5, c = i & 31;
                    uint32_t cph = (uint32_t)(c ^ (row & 7));
                    cp16(sb + (uint32_t)row * 1024 + cph * 16,
                         g_h + ((size_t)(p * NTOT) + m0 + row) * 256 + c * 8);
                }
                cp_commit();
                issue_b_chunk(bw_base, w1base, 0, lseed, ldst);
                issue_b_chunk(bw_base, w1base, 1, lseed, ldst);
#pragma unroll
                for (int mf = 0; mf < 4; mf++) {
                    int r = mf * 16 + (lane >> 2);
#pragma unroll
                    for (int nf = 0; nf < 8; nf++) {
                        int col = 256 + wn * 64 + nf * 8 + (lane & 3) * 2;
                        float2 bv = *(const float2*)(bias + col);
                        float* c4 = acc[mf][nf];
                        __half2 h0 = __floats2half2_rn(fmaxf(c4[0] + bv.x, 0.f),
                                                       fmaxf(c4[1] + bv.y, 0.f));
                        __half2 h1 = __floats2half2_rn(fmaxf(c4[2] + bv.x, 0.f),
                                                       fmaxf(c4[3] + bv.y, 0.f));
                        int ca = col >> 3;
                        uint32_t off = (uint32_t)r * 1024 +
                                       (uint32_t)((ca ^ (r & 7)) << 4) +
                                       (uint32_t)(lane & 3) * 4;
                        *(__half2*)(smem + off) = h0;
                        *(__half2*)(smem + off + 8192) = h1;   // row+8: same swizzle phase
                    }
                }
                cp_wait<2>();     // A reload landed
                __syncthreads();
            } else {
                // layer 1: fold into layer-2 dot
#pragma unroll
                for (int mf = 0; mf < 4; mf++) {
#pragma unroll
                    for (int nf = 0; nf < 8; nf++) {
                        int col = nch * 256 + wn * 64 + nf * 8 + (lane & 3) * 2;
                        float2 bv = *(const float2*)(bias + col);
                        float2 wv = *(const float2*)(w2g + col);
                        float* c4 = acc[mf][nf];
                        pacc[mf][0] = fmaf(fmaxf(c4[0] + bv.x, 0.f), wv.x,
                                      fmaf(fmaxf(c4[1] + bv.y, 0.f), wv.y, pacc[mf][0]));
                        pacc[mf][1] = fmaf(fmaxf(c4[2] + bv.x, 0.f), wv.x,
                                      fmaf(fmaxf(c4[3] + bv.y, 0.f), wv.y, pacc[mf][1]));
                    }
                }
            }
        }
    }

    // Final reduction (scratch reuses B region)
    __syncthreads();
    float* red = (float*)(smem + SB);
#pragma unroll
    for (int mf = 0; mf < 4; mf++)
#pragma unroll
        for (int rp = 0; rp < 2; rp++) {
            float v = pacc[mf][rp];
            v += __shfl_xor_sync(0xffffffffu, v, 1);
            v += __shfl_xor_sync(0xffffffffu, v, 2);
            if ((lane & 3) == 0) {
                int row = mf * 16 + rp * 8 + (lane >> 2);
                red[row * 4 + wn] = v;
            }
        }
    __syncthreads();
    if (tid < MT) {
        float z = red[tid * 4] + red[tid * 4 + 1] + red[tid * 4 + 2] + red[tid * 4 + 3] + b2[p];
        out[((size_t)(m0 + tid)) * PP + p] = 1.f / (1.f + __expf(-z));
    }
}

// ---------------------------------------------------------------------------
// Launch
// ---------------------------------------------------------------------------
extern "C" void kernel_launch(void* const* d_in, const int* in_sizes, int n_in,
                              void* d_out, int out_size) {
    const float* e  = (const float*)d_in[0];
    const float* W0 = (const float*)d_in[1];
    const float* b0 = (const float*)d_in[2];
    const float* W1 = (const float*)d_in[3];
    const float* b1 = (const float*)d_in[4];
    const float* W2 = (const float*)d_in[5];
    const float* b2 = (const float*)d_in[6];
    float* out = (float*)d_out;

    cudaFuncSetAttribute(mlp_fused, cudaFuncAttributeMaxDynamicSharedMemorySize, SMEM_BYTES);

    prepass_kernel<<<dim3(16, 16, 34), dim3(32, 8)>>>(e, W0, W1);
    mlp_fused<<<PP * (NTOT / MT), THREADS, SMEM_BYTES>>>(b0, b1, W2, b2, out);
}